// round 3
// baseline (speedup 1.0000x reference)
#include <cuda_runtime.h>
#include <math.h>

// Problem constants
#define BB 2
#define TT 2048
#define DD 1024
#define HH 4
#define DK 256
#define MSLOT 64
#define CHUNK 64
#define NC (TT/CHUNK)          // 32
#define NROWS (BB*TT)          // 4096
#define LOW 16

// Scratch (device globals: allocation-free rule)
__device__ float g_q[NROWS*DD];
__device__ float g_k[NROWS*DD];
__device__ float g_v[NROWS*DD];
__device__ float g_g[NROWS*DD];
__device__ float g_o[NROWS*DD];
__device__ float g_xo[NROWS*DD];
__device__ float g_tmp[NROWS*2*LOW];
__device__ float g_wk[BB*HH*TT*MSLOT];
__device__ float g_wv[BB*HH*TT*MSLOT];
__device__ float g_zk[BB*HH*TT*MSLOT];
__device__ float g_zv[BB*HH*TT*MSLOT];
__device__ float g_Kst[BB*HH*NC*MSLOT*DK];   // 64 MB
__device__ float g_Vst[BB*HH*NC*MSLOT*DK];   // 64 MB

// ---------------------------------------------------------------------------
// Generic fp32 GEMM: C[M,N] = A[M,K] @ B[K,N], row-major, M%128==0, N%128==0,
// K%16==0. 128x128 block tile, 256 threads, 8x8 micro-tile.
// ---------------------------------------------------------------------------
__global__ __launch_bounds__(256)
void gemm128_kernel(const float* __restrict__ A,
                    const float* __restrict__ B,
                    float* __restrict__ C, int N, int K) {
    __shared__ float As[16][132];
    __shared__ float Bs[16][132];
    const int tid = threadIdx.x;
    const int tx = tid & 15, ty = tid >> 4;
    const int row0 = blockIdx.y * 128;
    const int col0 = blockIdx.x * 128;

    float acc[8][8];
    #pragma unroll
    for (int i = 0; i < 8; i++)
        #pragma unroll
        for (int j = 0; j < 8; j++) acc[i][j] = 0.f;

    const int lr  = tid >> 1;          // 0..127 (A row)
    const int lk  = (tid & 1) << 3;    // 0 or 8 (A k-offset)
    const int bkr = tid >> 4;          // 0..15 (B k-row)
    const int bc  = (tid & 15) << 3;   // B col offset

    for (int k0 = 0; k0 < K; k0 += 16) {
        const float* ap = A + (size_t)(row0 + lr) * K + k0 + lk;
        float4 a0 = *(const float4*)ap;
        float4 a1 = *(const float4*)(ap + 4);
        As[lk+0][lr] = a0.x; As[lk+1][lr] = a0.y; As[lk+2][lr] = a0.z; As[lk+3][lr] = a0.w;
        As[lk+4][lr] = a1.x; As[lk+5][lr] = a1.y; As[lk+6][lr] = a1.z; As[lk+7][lr] = a1.w;
        const float* bp = B + (size_t)(k0 + bkr) * N + col0 + bc;
        *(float4*)&Bs[bkr][bc]     = *(const float4*)bp;
        *(float4*)&Bs[bkr][bc + 4] = *(const float4*)(bp + 4);
        __syncthreads();
        #pragma unroll
        for (int kk = 0; kk < 16; kk++) {
            float a[8], b[8];
            #pragma unroll
            for (int i = 0; i < 8; i++) a[i] = As[kk][ty*8 + i];
            #pragma unroll
            for (int j = 0; j < 8; j++) b[j] = Bs[kk][tx*8 + j];
            #pragma unroll
            for (int i = 0; i < 8; i++)
                #pragma unroll
                for (int j = 0; j < 8; j++) acc[i][j] += a[i]*b[j];
        }
        __syncthreads();
    }
    #pragma unroll
    for (int i = 0; i < 8; i++) {
        float* cp = C + (size_t)(row0 + ty*8 + i) * N + col0 + tx*8;
        #pragma unroll
        for (int j = 0; j < 8; j++) cp[j] = acc[i][j];
    }
}

// ---------------------------------------------------------------------------
// RoPE on q and k in place. One block per (row, head); thread j = rotation pair.
// Angles in fp64 to avoid trig drift (t up to 2047 radians).
// ---------------------------------------------------------------------------
__global__ void rope_kernel() {
    int row = blockIdx.x;          // b*T + t
    int h = blockIdx.y;
    int j = threadIdx.x;           // 0..127
    int t = row & (TT - 1);
    double invf = exp(-(double)j * 0.07195578415606393558); // ln(1e4)/128
    double ang = (double)t * invf;
    float c = (float)cos(ang);
    float s = (float)sin(ang);
    size_t base = (size_t)row * DD + h * DK;
    float q1 = g_q[base + j], q2 = g_q[base + 128 + j];
    g_q[base + j]       = q1*c - q2*s;
    g_q[base + 128 + j] = q2*c + q1*s;
    float k1 = g_k[base + j], k2 = g_k[base + 128 + j];
    g_k[base + j]       = k1*c - k2*s;
    g_k[base + 128 + j] = k2*c + k1*s;
}

// ---------------------------------------------------------------------------
// sk/sv stage 1: tmp[row, 0:16] = x_row @ sk_w1 ; tmp[row, 16:32] = x_row @ sv_w1
// Block: 8 rows x 32 cols (256 threads).
// ---------------------------------------------------------------------------
__global__ __launch_bounds__(256)
void skv1_kernel(const float* __restrict__ x,
                 const float* __restrict__ w1k,
                 const float* __restrict__ w1v) {
    __shared__ float ws[128][32];
    __shared__ float xs[8][128];
    int tid = threadIdx.x;
    int r = tid >> 5, cc = tid & 31;
    int row0 = blockIdx.x * 8;
    float acc = 0.f;
    for (int k0 = 0; k0 < DD; k0 += 128) {
        for (int i = tid; i < 128*32; i += 256) {
            int kk = i >> 5, c2 = i & 31;
            ws[kk][c2] = (c2 < 16) ? w1k[(k0+kk)*16 + c2]
                                   : w1v[(k0+kk)*16 + (c2-16)];
        }
        for (int i = tid; i < 8*128; i += 256)
            xs[i >> 7][i & 127] = x[(size_t)(row0 + (i >> 7)) * DD + k0 + (i & 127)];
        __syncthreads();
        #pragma unroll 8
        for (int kk = 0; kk < 128; kk++) acc += xs[r][kk] * ws[kk][cc];
        __syncthreads();
    }
    g_tmp[(size_t)(row0 + r) * 32 + cc] = acc;
}

// ---------------------------------------------------------------------------
// sk/sv stage 2: wk/wv = exp(clip(tmp @ w2 + b, +-32)), written in [B,H,T,M].
// One block per row, 256 threads = h*64+m.
// ---------------------------------------------------------------------------
__global__ void skv2_kernel(const float* __restrict__ w2k, const float* __restrict__ b2k,
                            const float* __restrict__ w2v, const float* __restrict__ b2v) {
    int row = blockIdx.x;
    int cidx = threadIdx.x;
    int b = row >> 11, t = row & 2047;
    int h = cidx >> 6, m = cidx & 63;
    float aK = b2k[cidx], aV = b2v[cidx];
    #pragma unroll
    for (int j = 0; j < 16; j++) {
        float tk = g_tmp[(size_t)row*32 + j];
        float tv = g_tmp[(size_t)row*32 + 16 + j];
        aK += tk * w2k[j*256 + cidx];
        aV += tv * w2v[j*256 + cidx];
    }
    aK = fminf(fmaxf(aK, -32.f), 32.f);
    aV = fminf(fmaxf(aV, -32.f), 32.f);
    size_t oi = ((size_t)((b*HH + h)*TT + t)) * MSLOT + m;
    g_wk[oi] = expf(aK);
    g_wv[oi] = expf(aV);
}

// ---------------------------------------------------------------------------
// Inclusive cumsum over t for zk/zv. Block per (b,h), y selects k/v; 64 threads (m).
// Unrolled x8 so 8 independent LDGs are in flight (dependence chain is the add).
// ---------------------------------------------------------------------------
__global__ void cumsum_kernel() {
    int bh = blockIdx.x;
    int m = threadIdx.x;
    const float* w = (blockIdx.y ? g_wv : g_wk) + (size_t)bh * TT * MSLOT;
    float*       z = (blockIdx.y ? g_zv : g_zk) + (size_t)bh * TT * MSLOT;
    float acc = 0.f;
    for (int t0 = 0; t0 < TT; t0 += 8) {
        float vals[8];
        #pragma unroll
        for (int u = 0; u < 8; u++)
            vals[u] = w[(size_t)(t0 + u) * MSLOT + m];
        #pragma unroll
        for (int u = 0; u < 8; u++) {
            acc += vals[u];
            z[(size_t)(t0 + u) * MSLOT + m] = acc;
        }
    }
}

// ---------------------------------------------------------------------------
// Phase A: per-chunk local states  St[m,d] = sum_{t in chunk} w[t,m] * kv[t,d]
// grid.x = B*H*NC (bhc), grid.y selects (K,k)/(V,v). 256 threads: d = tid.
// ---------------------------------------------------------------------------
__global__ __launch_bounds__(256)
void phaseA_kernel() {
    __shared__ float ws[CHUNK][MSLOT + 1];
    int bhc = blockIdx.x;
    int c = bhc % NC, bh = bhc / NC;
    int h = bh % HH, b = bh / HH;
    const float* w  = (blockIdx.y ? g_wv : g_wk) + ((size_t)bh*TT + c*CHUNK) * MSLOT;
    const float* kv = blockIdx.y ? g_v : g_k;
    float* st = (blockIdx.y ? g_Vst : g_Kst) + (size_t)bhc * MSLOT * DK;
    int tid = threadIdx.x;
    for (int i = tid; i < CHUNK*MSLOT; i += 256) ws[i >> 6][i & 63] = w[i];
    __syncthreads();
    float acc[MSLOT];
    #pragma unroll
    for (int m2 = 0; m2 < MSLOT; m2++) acc[m2] = 0.f;
    int d = tid;
    for (int t = 0; t < CHUNK; t++) {
        float val = kv[(size_t)(b*TT + c*CHUNK + t) * DD + h*DK + d];
        #pragma unroll
        for (int m2 = 0; m2 < MSLOT; m2++) acc[m2] += ws[t][m2] * val;
    }
    for (int m2 = 0; m2 < MSLOT; m2++) st[m2*DK + d] = acc[m2];
}

// ---------------------------------------------------------------------------
// Convert chunk-local states to EXCLUSIVE prefix over chunks (in place).
// grid: x covers m*DK, y = bh, z selects K/V.
// ---------------------------------------------------------------------------
__global__ void scan_kernel() {
    int md = blockIdx.x * 256 + threadIdx.x;
    int bh = blockIdx.y;
    float* st = (blockIdx.z ? g_Vst : g_Kst) + (size_t)bh * NC * MSLOT * DK + md;
    float run = 0.f;
    #pragma unroll 4
    for (int ci = 0; ci < NC; ci++) {
        float v = st[(size_t)ci * MSLOT * DK];
        st[(size_t)ci * MSLOT * DK] = run;
        run += v;
    }
}

// ---------------------------------------------------------------------------
// Phase B: per (b,h,chunk) block — intra-chunk attention + inter-chunk state.
//   logits = (tril(q k^T) @ wk + q @ Kprev^T) * scale / zk
//   p~ = softmax_m(logits) / zv
//   o  = tril(p~ @ wv^T) @ v + p~ @ Vprev
// 256 threads; dynamic smem.
// ---------------------------------------------------------------------------
#define SQS 257
#define SSS 65
#define PB_SMEM ((2*CHUNK*SQS + 3*CHUNK*SSS) * 4)

__global__ __launch_bounds__(256)
void phaseB_kernel() {
    extern __shared__ float sm[];
    float* sQ = sm;                    // [64][257] : q chunk, later v chunk
    float* sK = sm + CHUNK*SQS;        // [64][257] : k chunk, later Kprev/Vprev
    float* sS = sK + CHUNK*SQS;        // [64][65]  : Sloc, later A_intra
    float* sW = sS + CHUNK*SSS;        // [64][65]  : wk, later wv
    float* sP = sW + CHUNK*SSS;        // [64][65]  : logits -> p~

    int bhc = blockIdx.x;
    int c = bhc % NC, bh = bhc / NC;
    int h = bh % HH, b = bh / HH;
    int t0 = c * CHUNK;
    int tid = threadIdx.x;
    int tx = tid & 15, ty = tid >> 4;

    // load q, k chunks
    for (int i = tid; i < CHUNK*DK; i += 256) {
        int t = i >> 8, d = i & 255;
        size_t gi = (size_t)(b*TT + t0 + t) * DD + h*DK + d;
        sQ[t*SQS + d] = g_q[gi];
        sK[t*SQS + d] = g_k[gi];
    }
    __syncthreads();

    // Sloc = tril(q @ k^T): thread -> t = ty*4+i, s = tx+16*j
    float acc4[4][4];
    #pragma unroll
    for (int i = 0; i < 4; i++)
        #pragma unroll
        for (int j = 0; j < 4; j++) acc4[i][j] = 0.f;
    #pragma unroll 4
    for (int d = 0; d < DK; d++) {
        float a[4], bb[4];
        #pragma unroll
        for (int i = 0; i < 4; i++) a[i]  = sQ[(ty*4 + i)*SQS + d];
        #pragma unroll
        for (int j = 0; j < 4; j++) bb[j] = sK[(tx + 16*j)*SQS + d];
        #pragma unroll
        for (int i = 0; i < 4; i++)
            #pragma unroll
            for (int j = 0; j < 4; j++) acc4[i][j] += a[i]*bb[j];
    }
    #pragma unroll
    for (int i = 0; i < 4; i++)
        #pragma unroll
        for (int j = 0; j < 4; j++) {
            int t = ty*4 + i, s = tx + 16*j;
            sS[t*SSS + s] = (s <= t) ? acc4[i][j] : 0.f;
        }
    __syncthreads();

    // load wk -> sW, Kprev -> sK (k no longer needed)
    for (int i = tid; i < CHUNK*MSLOT; i += 256)
        sW[(i >> 6)*SSS + (i & 63)] = g_wk[((size_t)bh*TT + t0)*MSLOT + i];
    for (int i = tid; i < MSLOT*DK; i += 256)
        sK[(i >> 8)*SQS + (i & 255)] = g_Kst[(size_t)bhc*MSLOT*DK + i];
    __syncthreads();

    // logits[t][m] = Sloc @ wk + q @ Kprev^T, then * scale / zk
    #pragma unroll
    for (int i = 0; i < 4; i++)
        #pragma unroll
        for (int j = 0; j < 4; j++) acc4[i][j] = 0.f;
    #pragma unroll 4
    for (int s = 0; s < CHUNK; s++) {
        float a[4], bb[4];
        #pragma unroll
        for (int i = 0; i < 4; i++) a[i]  = sS[(ty*4 + i)*SSS + s];
        #pragma unroll
        for (int j = 0; j < 4; j++) bb[j] = sW[s*SSS + tx + 16*j];
        #pragma unroll
        for (int i = 0; i < 4; i++)
            #pragma unroll
            for (int j = 0; j < 4; j++) acc4[i][j] += a[i]*bb[j];
    }
    #pragma unroll 4
    for (int d = 0; d < DK; d++) {
        float a[4], bb[4];
        #pragma unroll
        for (int i = 0; i < 4; i++) a[i]  = sQ[(ty*4 + i)*SQS + d];
        #pragma unroll
        for (int j = 0; j < 4; j++) bb[j] = sK[(tx + 16*j)*SQS + d];
        #pragma unroll
        for (int i = 0; i < 4; i++)
            #pragma unroll
            for (int j = 0; j < 4; j++) acc4[i][j] += a[i]*bb[j];
    }
    #pragma unroll
    for (int i = 0; i < 4; i++)
        #pragma unroll
        for (int j = 0; j < 4; j++) {
            int t = ty*4 + i, m = tx + 16*j;
            float zk = g_zk[((size_t)bh*TT + t0 + t)*MSLOT + m];
            sP[t*SSS + m] = acc4[i][j] * 0.0625f / zk;
        }
    __syncthreads();

    // load wv -> sW, Vprev -> sK, v -> sQ (overlap with softmax below)
    for (int i = tid; i < CHUNK*MSLOT; i += 256)
        sW[(i >> 6)*SSS + (i & 63)] = g_wv[((size_t)bh*TT + t0)*MSLOT + i];
    for (int i = tid; i < MSLOT*DK; i += 256)
        sK[(i >> 8)*SQS + (i & 255)] = g_Vst[(size_t)bhc*MSLOT*DK + i];
    for (int i = tid; i < CHUNK*DK; i += 256) {
        int t = i >> 8, d = i & 255;
        sQ[t*SQS + d] = g_v[(size_t)(b*TT + t0 + t)*DD + h*DK + d];
    }

    // softmax over m per row, then divide by zv -> p~
    if (tid < CHUNK) {
        int t = tid;
        float mx = -1e30f;
        for (int m = 0; m < MSLOT; m++) mx = fmaxf(mx, sP[t*SSS + m]);
        float sum = 0.f;
        for (int m = 0; m < MSLOT; m++) {
            float e = expf(sP[t*SSS + m] - mx);
            sP[t*SSS + m] = e;
            sum += e;
        }
        float inv = 1.f / sum;
        for (int m = 0; m < MSLOT; m++) {
            float zv = g_zv[((size_t)bh*TT + t0 + t)*MSLOT + m];
            sP[t*SSS + m] *= inv / zv;
        }
    }
    __syncthreads();

    // A_intra = tril(p~ @ wv^T) -> sS
    #pragma unroll
    for (int i = 0; i < 4; i++)
        #pragma unroll
        for (int j = 0; j < 4; j++) acc4[i][j] = 0.f;
    #pragma unroll 4
    for (int mm = 0; mm < MSLOT; mm++) {
        float a[4], bb[4];
        #pragma unroll
        for (int i = 0; i < 4; i++) a[i]  = sP[(ty*4 + i)*SSS + mm];
        #pragma unroll
        for (int j = 0; j < 4; j++) bb[j] = sW[(tx + 16*j)*SSS + mm];
        #pragma unroll
        for (int i = 0; i < 4; i++)
            #pragma unroll
            for (int j = 0; j < 4; j++) acc4[i][j] += a[i]*bb[j];
    }
    __syncthreads();
    #pragma unroll
    for (int i = 0; i < 4; i++)
        #pragma unroll
        for (int j = 0; j < 4; j++) {
            int t = ty*4 + i, s = tx + 16*j;
            sS[t*SSS + s] = (s <= t) ? acc4[i][j] : 0.f;
        }
    __syncthreads();

    // o = A_intra @ v + p~ @ Vprev ; thread covers t = ty*4+i, d = tx + 16*jj
    float accO[4][16];
    #pragma unroll
    for (int i = 0; i < 4; i++)
        #pragma unroll
        for (int jj = 0; jj < 16; jj++) accO[i][jj] = 0.f;
    #pragma unroll 2
    for (int s = 0; s < CHUNK; s++) {
        float a[4];
        #pragma unroll
        for (int i = 0; i < 4; i++) a[i] = sS[(ty*4 + i)*SSS + s];
        float vv[16];
        #pragma unroll
        for (int jj = 0; jj < 16; jj++) vv[jj] = sQ[s*SQS + tx + 16*jj];
        #pragma unroll
        for (int i = 0; i < 4; i++)
            #pragma unroll
            for (int jj = 0; jj < 16; jj++) accO[i][jj] += a[i]*vv[jj];
    }
    #pragma unroll 2
    for (int mm = 0; mm < MSLOT; mm++) {
        float a[4];
        #pragma unroll
        for (int i = 0; i < 4; i++) a[i] = sP[(ty*4 + i)*SSS + mm];
        float vv[16];
        #pragma unroll
        for (int jj = 0; jj < 16; jj++) vv[jj] = sK[mm*SQS + tx + 16*jj];
        #pragma unroll
        for (int i = 0; i < 4; i++)
            #pragma unroll
            for (int jj = 0; jj < 16; jj++) accO[i][jj] += a[i]*vv[jj];
    }
    #pragma unroll
    for (int i = 0; i < 4; i++) {
        size_t base = (size_t)(b*TT + t0 + ty*4 + i)*DD + h*DK;
        #pragma unroll
        for (int jj = 0; jj < 16; jj++) g_o[base + tx + 16*jj] = accO[i][jj];
    }
}

// ---------------------------------------------------------------------------
// Gated RMSNorm: on = o * rsqrt(mean(o^2)+eps)*gnw ; xo = on * g * sigmoid(g)
// Block per row (b,t); warp per head.
// ---------------------------------------------------------------------------
__global__ void gate_kernel(const float* __restrict__ gnw) {
    int row = blockIdx.x;
    int w = threadIdx.x >> 5, lane = threadIdx.x & 31;
    size_t base = (size_t)row*DD + w*DK;
    float ss = 0.f;
    for (int j = lane; j < DK; j += 32) { float v = g_o[base + j]; ss += v*v; }
    #pragma unroll
    for (int off = 16; off; off >>= 1) ss += __shfl_xor_sync(0xffffffffu, ss, off);
    float r = 1.f / sqrtf(ss * (1.f/256.f) + 1e-5f);
    for (int j = lane; j < DK; j += 32) {
        float gv = g_g[base + j];
        float sig = 1.f / (1.f + expf(-gv));
        g_xo[base + j] = g_o[base + j] * r * gnw[j] * gv * sig;
    }
}

// ---------------------------------------------------------------------------
extern "C" void kernel_launch(void* const* d_in, const int* in_sizes, int n_in,
                              void* d_out, int out_size) {
    const float* x    = (const float*)d_in[0];
    const float* Wq   = (const float*)d_in[1];
    const float* Wk   = (const float*)d_in[2];
    const float* Wv   = (const float*)d_in[3];
    const float* Wg   = (const float*)d_in[4];
    const float* Wo   = (const float*)d_in[5];
    const float* skw1 = (const float*)d_in[6];
    const float* skw2 = (const float*)d_in[7];
    const float* skb2 = (const float*)d_in[8];
    const float* svw1 = (const float*)d_in[9];
    const float* svw2 = (const float*)d_in[10];
    const float* svb2 = (const float*)d_in[11];
    const float* gnw  = (const float*)d_in[12];
    float* out = (float*)d_out;

    float *pq, *pk, *pv, *pg, *pxo;
    cudaGetSymbolAddress((void**)&pq,  g_q);
    cudaGetSymbolAddress((void**)&pk,  g_k);
    cudaGetSymbolAddress((void**)&pv,  g_v);
    cudaGetSymbolAddress((void**)&pg,  g_g);
    cudaGetSymbolAddress((void**)&pxo, g_xo);

    dim3 ggrid(DD/128, NROWS/128);   // (8, 32)
    gemm128_kernel<<<ggrid, 256>>>(x, Wq, pq, DD, DD);
    gemm128_kernel<<<ggrid, 256>>>(x, Wk, pk, DD, DD);
    gemm128_kernel<<<ggrid, 256>>>(x, Wv, pv, DD, DD);
    gemm128_kernel<<<ggrid, 256>>>(x, Wg, pg, DD, DD);

    rope_kernel<<<dim3(NROWS, HH), 128>>>();

    skv1_kernel<<<NROWS/8, 256>>>(x, skw1, svw1);
    skv2_kernel<<<NROWS, 256>>>(skw2, skb2, svw2, svb2);
    cumsum_kernel<<<dim3(BB*HH, 2), 64>>>();

    phaseA_kernel<<<dim3(BB*HH*NC, 2), 256>>>();
    scan_kernel<<<dim3(MSLOT*DK/256, BB*HH, 2), 256>>>();

    cudaFuncSetAttribute(phaseB_kernel,
                         cudaFuncAttributeMaxDynamicSharedMemorySize, PB_SMEM);
    phaseB_kernel<<<BB*HH*NC, 256, PB_SMEM>>>();

    gate_kernel<<<NROWS, 128>>>(gnw);
    gemm128_kernel<<<ggrid, 256>>>(pxo, Wo, out, DD, DD);
}

// round 5
// speedup vs baseline: 1.3548x; 1.3548x over previous
#include <cuda_runtime.h>
#include <math.h>
#include <stdint.h>

// Problem constants
#define BB 2
#define TT 2048
#define DD 1024
#define HH 4
#define DK 256
#define MSLOT 64
#define CHUNK 64
#define NC (TT/CHUNK)          // 32
#define NROWS (BB*TT)          // 4096
#define LOW 16

// Scratch (device globals: allocation-free rule)
__device__ float g_q[NROWS*DD];
__device__ float g_k[NROWS*DD];
__device__ float g_v[NROWS*DD];
__device__ float g_g[NROWS*DD];
__device__ float g_o[NROWS*DD];
__device__ float g_xo[NROWS*DD];
__device__ float g_tmp[NROWS*2*LOW];
__device__ float g_wk[BB*HH*TT*MSLOT];
__device__ float g_wv[BB*HH*TT*MSLOT];
__device__ float g_zk[BB*HH*TT*MSLOT];
__device__ float g_zv[BB*HH*TT*MSLOT];
__device__ float g_Kst[BB*HH*NC*MSLOT*DK];   // 64 MB
__device__ float g_Vst[BB*HH*NC*MSLOT*DK];   // 64 MB

// ---------------------------------------------------------------------------
// Split-TF32 tensor-core GEMM: C[M,N] = A[M,K] @ B[K,N], row-major.
// M%128==0, N%128==0, K%16==0. 128x128 CTA tile, 256 threads (8 warps),
// warp tile 64x32 (4 m-tiles x 4 n-tiles of m16n8k8).
// Each operand split x = hi + lo (hi = mask low 13 mantissa bits);
// acc += Ah*Bh + Ah*Bl + Al*Bh  => ~fp32-grade precision on tensor cores.
// ---------------------------------------------------------------------------
#define AS_STR 20    // As row stride (floats): conflict-free frag reads
#define BS_STR 136   // Bs row stride (floats): conflict-free frag reads

#define MMA_TF32(d, a0,a1,a2,a3, b0,b1) \
  asm volatile("mma.sync.aligned.m16n8k8.row.col.f32.tf32.tf32.f32 " \
    "{%0,%1,%2,%3}, {%4,%5,%6,%7}, {%8,%9}, {%0,%1,%2,%3};" \
    : "+f"(d[0]), "+f"(d[1]), "+f"(d[2]), "+f"(d[3]) \
    : "r"(a0), "r"(a1), "r"(a2), "r"(a3), "r"(b0), "r"(b1))

#define CPA16(dst, src) \
  asm volatile("cp.async.cg.shared.global [%0], [%1], 16;" \
               :: "r"(dst), "l"(src) : "memory")

__global__ __launch_bounds__(256)
void gemm_tf32_kernel(const float* __restrict__ A,
                      const float* __restrict__ B,
                      float* __restrict__ C, int N, int K) {
    __shared__ float As[2][128*AS_STR];
    __shared__ float Bs[2][16*BS_STR];

    const int tid  = threadIdx.x;
    const int warp = tid >> 5, lane = tid & 31;
    const int g    = lane >> 2, tig = lane & 3;
    const int wm   = warp & 1,  wn  = warp >> 1;
    const int rowBase = blockIdx.y * 128;
    const int colBase = blockIdx.x * 128;

    // global->smem copy mapping (per ktile of 16)
    const int ar = tid >> 1, ak = (tid & 1) << 3;   // A: 128 rows x 16 k
    const int br = tid >> 4, bc = (tid & 15) << 3;  // B: 16 rows  x 128 n

    const float* Ag = A + (size_t)(rowBase + ar) * K + ak;
    const float* Bg = B + (size_t)br * N + colBase + bc;

    unsigned sa0 = (unsigned)__cvta_generic_to_shared(&As[0][ar*AS_STR + ak]);
    unsigned sa1 = (unsigned)__cvta_generic_to_shared(&As[1][ar*AS_STR + ak]);
    unsigned sb0 = (unsigned)__cvta_generic_to_shared(&Bs[0][br*BS_STR + bc]);
    unsigned sb1 = (unsigned)__cvta_generic_to_shared(&Bs[1][br*BS_STR + bc]);

    // prologue: stage 0
    CPA16(sa0,      Ag);     CPA16(sa0 + 16, Ag + 4);
    CPA16(sb0,      Bg);     CPA16(sb0 + 16, Bg + 4);
    asm volatile("cp.async.commit_group;" ::: "memory");

    float acc[4][4][4];
    #pragma unroll
    for (int mt = 0; mt < 4; mt++)
        #pragma unroll
        for (int nt = 0; nt < 4; nt++)
            #pragma unroll
            for (int r = 0; r < 4; r++) acc[mt][nt][r] = 0.f;

    const int nk = K >> 4;
    for (int kt = 0; kt < nk; kt++) {
        asm volatile("cp.async.wait_group 0;" ::: "memory");
        __syncthreads();
        const int cur = kt & 1;
        if (kt + 1 < nk) {
            const float* Ag2 = Ag + (kt + 1) * 16;
            const float* Bg2 = Bg + (size_t)(kt + 1) * 16 * N;
            unsigned da = cur ? sa0 : sa1;
            unsigned db = cur ? sb0 : sb1;
            CPA16(da,      Ag2);     CPA16(da + 16, Ag2 + 4);
            CPA16(db,      Bg2);     CPA16(db + 16, Bg2 + 4);
            asm volatile("cp.async.commit_group;" ::: "memory");
        }
        const float* as = As[cur];
        const float* bs = Bs[cur];

        #pragma unroll
        for (int ko = 0; ko < 16; ko += 8) {
            // --- load + split A fragments ---
            unsigned ah[4][4]; unsigned alb[4][4];
            #pragma unroll
            for (int mt = 0; mt < 4; mt++) {
                const int r0 = wm*64 + mt*16 + g;
                float f[4];
                f[0] = as[r0*AS_STR + ko + tig];
                f[1] = as[(r0+8)*AS_STR + ko + tig];
                f[2] = as[r0*AS_STR + ko + tig + 4];
                f[3] = as[(r0+8)*AS_STR + ko + tig + 4];
                #pragma unroll
                for (int r = 0; r < 4; r++) {
                    unsigned hi = __float_as_uint(f[r]) & 0xFFFFE000u;
                    ah[mt][r]  = hi;
                    alb[mt][r] = __float_as_uint(f[r] - __uint_as_float(hi));
                }
            }
            // --- load + split B fragments ---
            unsigned bh[4][2]; unsigned blb[4][2];
            #pragma unroll
            for (int nt = 0; nt < 4; nt++) {
                const int cb = wn*32 + nt*8 + g;
                float f0 = bs[(ko + tig)*BS_STR + cb];
                float f1 = bs[(ko + tig + 4)*BS_STR + cb];
                unsigned h0 = __float_as_uint(f0) & 0xFFFFE000u;
                unsigned h1 = __float_as_uint(f1) & 0xFFFFE000u;
                bh[nt][0] = h0; bh[nt][1] = h1;
                blb[nt][0] = __float_as_uint(f0 - __uint_as_float(h0));
                blb[nt][1] = __float_as_uint(f1 - __uint_as_float(h1));
            }
            // --- 3-term MMAs ---
            #pragma unroll
            for (int mt = 0; mt < 4; mt++)
                #pragma unroll
                for (int nt = 0; nt < 4; nt++) {
                    MMA_TF32(acc[mt][nt], ah[mt][0], ah[mt][1], ah[mt][2], ah[mt][3],
                             blb[nt][0], blb[nt][1]);
                    MMA_TF32(acc[mt][nt], alb[mt][0], alb[mt][1], alb[mt][2], alb[mt][3],
                             bh[nt][0], bh[nt][1]);
                    MMA_TF32(acc[mt][nt], ah[mt][0], ah[mt][1], ah[mt][2], ah[mt][3],
                             bh[nt][0], bh[nt][1]);
                }
        }
    }

    // epilogue
    #pragma unroll
    for (int mt = 0; mt < 4; mt++) {
        const int row = rowBase + wm*64 + mt*16 + g;
        #pragma unroll
        for (int nt = 0; nt < 4; nt++) {
            const int col = colBase + wn*32 + nt*8 + tig*2;
            float2 v0 = make_float2(acc[mt][nt][0], acc[mt][nt][1]);
            float2 v1 = make_float2(acc[mt][nt][2], acc[mt][nt][3]);
            *(float2*)&C[(size_t)row*N + col]     = v0;
            *(float2*)&C[(size_t)(row+8)*N + col] = v1;
        }
    }
}

// ---------------------------------------------------------------------------
// RoPE on q and k in place. One block per (row, head); thread j = rotation pair.
// Angles in fp64 to avoid trig drift (t up to 2047 radians).
// ---------------------------------------------------------------------------
__global__ void rope_kernel() {
    int row = blockIdx.x;          // b*T + t
    int h = blockIdx.y;
    int j = threadIdx.x;           // 0..127
    int t = row & (TT - 1);
    double invf = exp(-(double)j * 0.07195578415606393558); // ln(1e4)/128
    double ang = (double)t * invf;
    float c = (float)cos(ang);
    float s = (float)sin(ang);
    size_t base = (size_t)row * DD + h * DK;
    float q1 = g_q[base + j], q2 = g_q[base + 128 + j];
    g_q[base + j]       = q1*c - q2*s;
    g_q[base + 128 + j] = q2*c + q1*s;
    float k1 = g_k[base + j], k2 = g_k[base + 128 + j];
    g_k[base + j]       = k1*c - k2*s;
    g_k[base + 128 + j] = k2*c + k1*s;
}

// ---------------------------------------------------------------------------
// sk/sv stage 1: tmp[row, 0:16] = x_row @ sk_w1 ; tmp[row, 16:32] = x_row @ sv_w1
// ---------------------------------------------------------------------------
__global__ __launch_bounds__(256)
void skv1_kernel(const float* __restrict__ x,
                 const float* __restrict__ w1k,
                 const float* __restrict__ w1v) {
    __shared__ float ws[128][32];
    __shared__ float xs[8][128];
    int tid = threadIdx.x;
    int r = tid >> 5, cc = tid & 31;
    int row0 = blockIdx.x * 8;
    float acc = 0.f;
    for (int k0 = 0; k0 < DD; k0 += 128) {
        for (int i = tid; i < 128*32; i += 256) {
            int kk = i >> 5, c2 = i & 31;
            ws[kk][c2] = (c2 < 16) ? w1k[(k0+kk)*16 + c2]
                                   : w1v[(k0+kk)*16 + (c2-16)];
        }
        for (int i = tid; i < 8*128; i += 256)
            xs[i >> 7][i & 127] = x[(size_t)(row0 + (i >> 7)) * DD + k0 + (i & 127)];
        __syncthreads();
        #pragma unroll 8
        for (int kk = 0; kk < 128; kk++) acc += xs[r][kk] * ws[kk][cc];
        __syncthreads();
    }
    g_tmp[(size_t)(row0 + r) * 32 + cc] = acc;
}

// ---------------------------------------------------------------------------
// sk/sv stage 2: wk/wv = exp(clip(tmp @ w2 + b, +-32)), written in [B,H,T,M].
// ---------------------------------------------------------------------------
__global__ void skv2_kernel(const float* __restrict__ w2k, const float* __restrict__ b2k,
                            const float* __restrict__ w2v, const float* __restrict__ b2v) {
    int row = blockIdx.x;
    int cidx = threadIdx.x;
    int b = row >> 11, t = row & 2047;
    int h = cidx >> 6, m = cidx & 63;
    float aK = b2k[cidx], aV = b2v[cidx];
    #pragma unroll
    for (int j = 0; j < 16; j++) {
        float tk = g_tmp[(size_t)row*32 + j];
        float tv = g_tmp[(size_t)row*32 + 16 + j];
        aK += tk * w2k[j*256 + cidx];
        aV += tv * w2v[j*256 + cidx];
    }
    aK = fminf(fmaxf(aK, -32.f), 32.f);
    aV = fminf(fmaxf(aV, -32.f), 32.f);
    size_t oi = ((size_t)((b*HH + h)*TT + t)) * MSLOT + m;
    g_wk[oi] = expf(aK);
    g_wv[oi] = expf(aV);
}

// ---------------------------------------------------------------------------
// Inclusive cumsum over t for zk/zv.
// ---------------------------------------------------------------------------
__global__ void cumsum_kernel() {
    int bh = blockIdx.x;
    int m = threadIdx.x;
    const float* w = (blockIdx.y ? g_wv : g_wk) + (size_t)bh * TT * MSLOT;
    float*       z = (blockIdx.y ? g_zv : g_zk) + (size_t)bh * TT * MSLOT;
    float acc = 0.f;
    for (int t0 = 0; t0 < TT; t0 += 8) {
        float vals[8];
        #pragma unroll
        for (int u = 0; u < 8; u++)
            vals[u] = w[(size_t)(t0 + u) * MSLOT + m];
        #pragma unroll
        for (int u = 0; u < 8; u++) {
            acc += vals[u];
            z[(size_t)(t0 + u) * MSLOT + m] = acc;
        }
    }
}

// ---------------------------------------------------------------------------
// Phase A: per-chunk local states  St[m,d] = sum_{t in chunk} w[t,m] * kv[t,d]
// ---------------------------------------------------------------------------
__global__ __launch_bounds__(256)
void phaseA_kernel() {
    __shared__ float ws[CHUNK][MSLOT + 1];
    int bhc = blockIdx.x;
    int c = bhc % NC, bh = bhc / NC;
    int h = bh % HH, b = bh / HH;
    const float* w  = (blockIdx.y ? g_wv : g_wk) + ((size_t)bh*TT + c*CHUNK) * MSLOT;
    const float* kv = blockIdx.y ? g_v : g_k;
    float* st = (blockIdx.y ? g_Vst : g_Kst) + (size_t)bhc * MSLOT * DK;
    int tid = threadIdx.x;
    for (int i = tid; i < CHUNK*MSLOT; i += 256) ws[i >> 6][i & 63] = w[i];
    __syncthreads();
    float acc[MSLOT];
    #pragma unroll
    for (int m2 = 0; m2 < MSLOT; m2++) acc[m2] = 0.f;
    int d = tid;
    for (int t = 0; t < CHUNK; t++) {
        float val = kv[(size_t)(b*TT + c*CHUNK + t) * DD + h*DK + d];
        #pragma unroll
        for (int m2 = 0; m2 < MSLOT; m2++) acc[m2] += ws[t][m2] * val;
    }
    for (int m2 = 0; m2 < MSLOT; m2++) st[m2*DK + d] = acc[m2];
}

// ---------------------------------------------------------------------------
// Convert chunk-local states to EXCLUSIVE prefix over chunks (in place).
// ---------------------------------------------------------------------------
__global__ void scan_kernel() {
    int md = blockIdx.x * 256 + threadIdx.x;
    int bh = blockIdx.y;
    float* st = (blockIdx.z ? g_Vst : g_Kst) + (size_t)bh * NC * MSLOT * DK + md;
    float run = 0.f;
    #pragma unroll 4
    for (int ci = 0; ci < NC; ci++) {
        float v = st[(size_t)ci * MSLOT * DK];
        st[(size_t)ci * MSLOT * DK] = run;
        run += v;
    }
}

// ---------------------------------------------------------------------------
// Phase B: per (b,h,chunk) block — intra-chunk attention + inter-chunk state.
// ---------------------------------------------------------------------------
#define SQS 257
#define SSS 65
#define PB_SMEM ((2*CHUNK*SQS + 3*CHUNK*SSS) * 4)

__global__ __launch_bounds__(256)
void phaseB_kernel() {
    extern __shared__ float sm[];
    float* sQ = sm;                    // [64][257] : q chunk, later v chunk
    float* sK = sm + CHUNK*SQS;        // [64][257] : k chunk, later Kprev/Vprev
    float* sS = sK + CHUNK*SQS;        // [64][65]  : Sloc, later A_intra
    float* sW = sS + CHUNK*SSS;        // [64][65]  : wk, later wv
    float* sP = sW + CHUNK*SSS;        // [64][65]  : logits -> p~

    int bhc = blockIdx.x;
    int c = bhc % NC, bh = bhc / NC;
    int h = bh % HH, b = bh / HH;
    int t0 = c * CHUNK;
    int tid = threadIdx.x;
    int tx = tid & 15, ty = tid >> 4;

    for (int i = tid; i < CHUNK*DK; i += 256) {
        int t = i >> 8, d = i & 255;
        size_t gi = (size_t)(b*TT + t0 + t) * DD + h*DK + d;
        sQ[t*SQS + d] = g_q[gi];
        sK[t*SQS + d] = g_k[gi];
    }
    __syncthreads();

    float acc4[4][4];
    #pragma unroll
    for (int i = 0; i < 4; i++)
        #pragma unroll
        for (int j = 0; j < 4; j++) acc4[i][j] = 0.f;
    #pragma unroll 4
    for (int d = 0; d < DK; d++) {
        float a[4], bb[4];
        #pragma unroll
        for (int i = 0; i < 4; i++) a[i]  = sQ[(ty*4 + i)*SQS + d];
        #pragma unroll
        for (int j = 0; j < 4; j++) bb[j] = sK[(tx + 16*j)*SQS + d];
        #pragma unroll
        for (int i = 0; i < 4; i++)
            #pragma unroll
            for (int j = 0; j < 4; j++) acc4[i][j] += a[i]*bb[j];
    }
    #pragma unroll
    for (int i = 0; i < 4; i++)
        #pragma unroll
        for (int j = 0; j < 4; j++) {
            int t = ty*4 + i, s = tx + 16*j;
            sS[t*SSS + s] = (s <= t) ? acc4[i][j] : 0.f;
        }
    __syncthreads();

    for (int i = tid; i < CHUNK*MSLOT; i += 256)
        sW[(i >> 6)*SSS + (i & 63)] = g_wk[((size_t)bh*TT + t0)*MSLOT + i];
    for (int i = tid; i < MSLOT*DK; i += 256)
        sK[(i >> 8)*SQS + (i & 255)] = g_Kst[(size_t)bhc*MSLOT*DK + i];
    __syncthreads();

    #pragma unroll
    for (int i = 0; i < 4; i++)
        #pragma unroll
        for (int j = 0; j < 4; j++) acc4[i][j] = 0.f;
    #pragma unroll 4
    for (int s = 0; s < CHUNK; s++) {
        float a[4], bb[4];
        #pragma unroll
        for (int i = 0; i < 4; i++) a[i]  = sS[(ty*4 + i)*SSS + s];
        #pragma unroll
        for (int j = 0; j < 4; j++) bb[j] = sW[s*SSS + tx + 16*j];
        #pragma unroll
        for (int i = 0; i < 4; i++)
            #pragma unroll
            for (int j = 0; j < 4; j++) acc4[i][j] += a[i]*bb[j];
    }
    #pragma unroll 4
    for (int d = 0; d < DK; d++) {
        float a[4], bb[4];
        #pragma unroll
        for (int i = 0; i < 4; i++) a[i]  = sQ[(ty*4 + i)*SQS + d];
        #pragma unroll
        for (int j = 0; j < 4; j++) bb[j] = sK[(tx + 16*j)*SQS + d];
        #pragma unroll
        for (int i = 0; i < 4; i++)
            #pragma unroll
            for (int j = 0; j < 4; j++) acc4[i][j] += a[i]*bb[j];
    }
    #pragma unroll
    for (int i = 0; i < 4; i++)
        #pragma unroll
        for (int j = 0; j < 4; j++) {
            int t = ty*4 + i, m = tx + 16*j;
            float zk = g_zk[((size_t)bh*TT + t0 + t)*MSLOT + m];
            sP[t*SSS + m] = acc4[i][j] * 0.0625f / zk;
        }
    __syncthreads();

    for (int i = tid; i < CHUNK*MSLOT; i += 256)
        sW[(i >> 6)*SSS + (i & 63)] = g_wv[((size_t)bh*TT + t0)*MSLOT + i];
    for (int i = tid; i < MSLOT*DK; i += 256)
        sK[(i >> 8)*SQS + (i & 255)] = g_Vst[(size_t)bhc*MSLOT*DK + i];
    for (int i = tid; i < CHUNK*DK; i += 256) {
        int t = i >> 8, d = i & 255;
        sQ[t*SQS + d] = g_v[(size_t)(b*TT + t0 + t)*DD + h*DK + d];
    }

    if (tid < CHUNK) {
        int t = tid;
        float mx = -1e30f;
        for (int m = 0; m < MSLOT; m++) mx = fmaxf(mx, sP[t*SSS + m]);
        float sum = 0.f;
        for (int m = 0; m < MSLOT; m++) {
            float e = expf(sP[t*SSS + m] - mx);
            sP[t*SSS + m] = e;
            sum += e;
        }
        float inv = 1.f / sum;
        for (int m = 0; m < MSLOT; m++) {
            float zv = g_zv[((size_t)bh*TT + t0 + t)*MSLOT + m];
            sP[t*SSS + m] *= inv / zv;
        }
    }
    __syncthreads();

    #pragma unroll
    for (int i = 0; i < 4; i++)
        #pragma unroll
        for (int j = 0; j < 4; j++) acc4[i][j] = 0.f;
    #pragma unroll 4
    for (int mm = 0; mm < MSLOT; mm++) {
        float a[4], bb[4];
        #pragma unroll
        for (int i = 0; i < 4; i++) a[i]  = sP[(ty*4 + i)*SSS + mm];
        #pragma unroll
        for (int j = 0; j < 4; j++) bb[j] = sW[(tx + 16*j)*SSS + mm];
        #pragma unroll
        for (int i = 0; i < 4; i++)
            #pragma unroll
            for (int j = 0; j < 4; j++) acc4[i][j] += a[i]*bb[j];
    }
    __syncthreads();
    #pragma unroll
    for (int i = 0; i < 4; i++)
        #pragma unroll
        for (int j = 0; j < 4; j++) {
            int t = ty*4 + i, s = tx + 16*j;
            sS[t*SSS + s] = (s <= t) ? acc4[i][j] : 0.f;
        }
    __syncthreads();

    float accO[4][16];
    #pragma unroll
    for (int i = 0; i < 4; i++)
        #pragma unroll
        for (int jj = 0; jj < 16; jj++) accO[i][jj] = 0.f;
    #pragma unroll 2
    for (int s = 0; s < CHUNK; s++) {
        float a[4];
        #pragma unroll
        for (int i = 0; i < 4; i++) a[i] = sS[(ty*4 + i)*SSS + s];
        float vv[16];
        #pragma unroll
        for (int jj = 0; jj < 16; jj++) vv[jj] = sQ[s*SQS + tx + 16*jj];
        #pragma unroll
        for (int i = 0; i < 4; i++)
            #pragma unroll
            for (int jj = 0; jj < 16; jj++) accO[i][jj] += a[i]*vv[jj];
    }
    #pragma unroll 2
    for (int mm = 0; mm < MSLOT; mm++) {
        float a[4];
        #pragma unroll
        for (int i = 0; i < 4; i++) a[i] = sP[(ty*4 + i)*SSS + mm];
        float vv[16];
        #pragma unroll
        for (int jj = 0; jj < 16; jj++) vv[jj] = sK[mm*SQS + tx + 16*jj];
        #pragma unroll
        for (int i = 0; i < 4; i++)
            #pragma unroll
            for (int jj = 0; jj < 16; jj++) accO[i][jj] += a[i]*vv[jj];
    }
    #pragma unroll
    for (int i = 0; i < 4; i++) {
        size_t base = (size_t)(b*TT + t0 + ty*4 + i)*DD + h*DK;
        #pragma unroll
        for (int jj = 0; jj < 16; jj++) g_o[base + tx + 16*jj] = accO[i][jj];
    }
}

// ---------------------------------------------------------------------------
// Gated RMSNorm: on = o * rsqrt(mean(o^2)+eps)*gnw ; xo = on * g * sigmoid(g)
// ---------------------------------------------------------------------------
__global__ void gate_kernel(const float* __restrict__ gnw) {
    int row = blockIdx.x;
    int w = threadIdx.x >> 5, lane = threadIdx.x & 31;
    size_t base = (size_t)row*DD + w*DK;
    float ss = 0.f;
    for (int j = lane; j < DK; j += 32) { float v = g_o[base + j]; ss += v*v; }
    #pragma unroll
    for (int off = 16; off; off >>= 1) ss += __shfl_xor_sync(0xffffffffu, ss, off);
    float r = 1.f / sqrtf(ss * (1.f/256.f) + 1e-5f);
    for (int j = lane; j < DK; j += 32) {
        float gv = g_g[base + j];
        float sig = 1.f / (1.f + expf(-gv));
        g_xo[base + j] = g_o[base + j] * r * gnw[j] * gv * sig;
    }
}

// ---------------------------------------------------------------------------
extern "C" void kernel_launch(void* const* d_in, const int* in_sizes, int n_in,
                              void* d_out, int out_size) {
    const float* x    = (const float*)d_in[0];
    const float* Wq   = (const float*)d_in[1];
    const float* Wk   = (const float*)d_in[2];
    const float* Wv   = (const float*)d_in[3];
    const float* Wg   = (const float*)d_in[4];
    const float* Wo   = (const float*)d_in[5];
    const float* skw1 = (const float*)d_in[6];
    const float* skw2 = (const float*)d_in[7];
    const float* skb2 = (const float*)d_in[8];
    const float* svw1 = (const float*)d_in[9];
    const float* svw2 = (const float*)d_in[10];
    const float* svb2 = (const float*)d_in[11];
    const float* gnw  = (const float*)d_in[12];
    float* out = (float*)d_out;

    float *pq, *pk, *pv, *pg, *pxo;
    cudaGetSymbolAddress((void**)&pq,  g_q);
    cudaGetSymbolAddress((void**)&pk,  g_k);
    cudaGetSymbolAddress((void**)&pv,  g_v);
    cudaGetSymbolAddress((void**)&pg,  g_g);
    cudaGetSymbolAddress((void**)&pxo, g_xo);

    dim3 ggrid(DD/128, NROWS/128);   // (8, 32)
    gemm_tf32_kernel<<<ggrid, 256>>>(x, Wq, pq, DD, DD);
    gemm_tf32_kernel<<<ggrid, 256>>>(x, Wk, pk, DD, DD);
    gemm_tf32_kernel<<<ggrid, 256>>>(x, Wv, pv, DD, DD);
    gemm_tf32_kernel<<<ggrid, 256>>>(x, Wg, pg, DD, DD);

    rope_kernel<<<dim3(NROWS, HH), 128>>>();

    skv1_kernel<<<NROWS/8, 256>>>(x, skw1, svw1);
    skv2_kernel<<<NROWS, 256>>>(skw2, skb2, svw2, svb2);
    cumsum_kernel<<<dim3(BB*HH, 2), 64>>>();

    phaseA_kernel<<<dim3(BB*HH*NC, 2), 256>>>();
    scan_kernel<<<dim3(MSLOT*DK/256, BB*HH, 2), 256>>>();

    cudaFuncSetAttribute(phaseB_kernel,
                         cudaFuncAttributeMaxDynamicSharedMemorySize, PB_SMEM);
    phaseB_kernel<<<BB*HH*NC, 256, PB_SMEM>>>();

    gate_kernel<<<NROWS, 128>>>(gnw);
    gemm_tf32_kernel<<<ggrid, 256>>>(pxo, Wo, out, DD, DD);
}